// round 16
// baseline (speedup 1.0000x reference)
#include <cuda_runtime.h>
#include <cuda_fp16.h>
#include <cstdint>

#define NB   8
#define NC   64
#define NPTS 65536
#define RR   32
#define R3   32768

// Scratch (device globals — no allocation allowed)
__device__ __half2      g_voxh[NB * R3 * 32];    // fp16 voxel sums, 32 MiB
__device__ float        g_cnt[NB * R3];          // counts
__device__ double       g_sum[2][NB][3];         // coord sums (t=0: x1, t=1: x2)
__device__ unsigned int g_maxn[2][NB];           // max ||c-mean||^2 as float bits

__device__ __forceinline__ double warpRedSumD(double v) {
    #pragma unroll
    for (int o = 16; o > 0; o >>= 1) v += __shfl_down_sync(0xffffffffu, v, o);
    return v;
}
__device__ __forceinline__ float warpRedMaxF(float v) {
    #pragma unroll
    for (int o = 16; o > 0; o >>= 1) v = fmaxf(v, __shfl_down_sync(0xffffffffu, v, o));
    return v;
}

// ---------------------------------------------------------------- stats: sums
__global__ void sums_kernel(const float* __restrict__ c1, const float* __restrict__ c2) {
    const int t = blockIdx.z, b = blockIdx.y;
    const float* c = (t == 0 ? c1 : c2) + (size_t)b * 3 * NPTS;
    double sx = 0.0, sy = 0.0, sz = 0.0;
    for (int i = blockIdx.x * blockDim.x + threadIdx.x; i < NPTS; i += gridDim.x * blockDim.x) {
        sx += (double)c[i];
        sy += (double)c[NPTS + i];
        sz += (double)c[2 * NPTS + i];
    }
    sx = warpRedSumD(sx); sy = warpRedSumD(sy); sz = warpRedSumD(sz);
    __shared__ double sh[3][8];
    const int w = threadIdx.x >> 5, l = threadIdx.x & 31;
    if (l == 0) { sh[0][w] = sx; sh[1][w] = sy; sh[2][w] = sz; }
    __syncthreads();
    if (threadIdx.x == 0) {
        double a = 0, d = 0, e = 0;
        #pragma unroll
        for (int i = 0; i < 8; i++) { a += sh[0][i]; d += sh[1][i]; e += sh[2][i]; }
        atomicAdd(&g_sum[t][b][0], a);
        atomicAdd(&g_sum[t][b][1], d);
        atomicAdd(&g_sum[t][b][2], e);
    }
}

// ----------------------------------------------------------- stats: max norm^2
__global__ void maxnorm_kernel(const float* __restrict__ c1, const float* __restrict__ c2) {
    const int t = blockIdx.z, b = blockIdx.y;
    const float* c = (t == 0 ? c1 : c2) + (size_t)b * 3 * NPTS;
    const float mx = (float)(g_sum[t][b][0] * (1.0 / NPTS));
    const float my = (float)(g_sum[t][b][1] * (1.0 / NPTS));
    const float mz = (float)(g_sum[t][b][2] * (1.0 / NPTS));
    float m = 0.0f;
    for (int i = blockIdx.x * blockDim.x + threadIdx.x; i < NPTS; i += gridDim.x * blockDim.x) {
        const float dx = c[i] - mx, dy = c[NPTS + i] - my, dz = c[2 * NPTS + i] - mz;
        m = fmaxf(m, dx * dx + dy * dy + dz * dz);
    }
    m = warpRedMaxF(m);
    __shared__ float sh[8];
    const int w = threadIdx.x >> 5, l = threadIdx.x & 31;
    if (l == 0) sh[w] = m;
    __syncthreads();
    if (threadIdx.x == 0) {
        float mm = sh[0];
        #pragma unroll
        for (int i = 1; i < 8; i++) mm = fmaxf(mm, sh[i]);
        atomicMax(&g_maxn[t][b], __float_as_uint(mm));
    }
}

// --------------------------- x1 -> out passthrough copy (overlap stream)
// Block: 256 threads copies a 128-point x 64-channel tile, float4 both ways.
__global__ __launch_bounds__(256) void copy_kernel(const float* __restrict__ f1,
                                                   float* __restrict__ out) {
    const int b  = blockIdx.y;
    const int n0 = blockIdx.x * 128;
    const int tid = threadIdx.x;
    const float* f1b = f1 + (size_t)b * NC * NPTS;
    float* outb = out + (size_t)b * 2 * NC * NPTS;
    #pragma unroll
    for (int i = tid; i < 64 * 32; i += 256) {
        const int c = i >> 5, j = i & 31;
        const float4 v = ((const float4*)(f1b + (size_t)c * NPTS + n0))[j];
        __stcs(((float4*)(outb + (size_t)c * NPTS + n0)) + j, v);
    }
}

// -------------------------------------------------------------- voxelize (x2)
// Block: 256 threads, 32 points. Warp w handles channels 8w..8w+7, lane = point.
// fp16x2 vector reduction: one REDG.128 covers 8 channels.
__global__ __launch_bounds__(256) void vox_kernel(const float* __restrict__ f2,
                                                  const float* __restrict__ c2) {
    const int b  = blockIdx.y;
    const int n0 = blockIdx.x * 32;
    __shared__ int sv[32];
    const int tid = threadIdx.x;

    if (tid < 32) {
        const float* cb = c2 + (size_t)b * 3 * NPTS;
        const float mx = (float)(g_sum[1][b][0] * (1.0 / NPTS));
        const float my = (float)(g_sum[1][b][1] * (1.0 / NPTS));
        const float mz = (float)(g_sum[1][b][2] * (1.0 / NPTS));
        const float k  = 32.0f / (2.0f * sqrtf(__uint_as_float(g_maxn[1][b])));
        const int n = n0 + tid;
        const float ncx = fminf(fmaxf((cb[n]            - mx) * k + 16.0f, 0.0f), 31.0f);
        const float ncy = fminf(fmaxf((cb[NPTS + n]     - my) * k + 16.0f, 0.0f), 31.0f);
        const float ncz = fminf(fmaxf((cb[2 * NPTS + n] - mz) * k + 16.0f, 0.0f), 31.0f);
        const int v = ((int)rintf(ncx) * RR + (int)rintf(ncy)) * RR + (int)rintf(ncz);
        sv[tid] = v;
        atomicAdd(&g_cnt[b * R3 + v], 1.0f);
    }
    __syncthreads();

    const int w = tid >> 5, l = tid & 31;   // w: 0..7 channel groups of 8
    const int n = n0 + l;
    const float* fb = f2 + (size_t)b * NC * NPTS + (size_t)(8 * w) * NPTS + n;
    float f[8];
    #pragma unroll
    for (int j = 0; j < 8; ++j) f[j] = fb[(size_t)j * NPTS];

    __half2 h0 = __floats2half2_rn(f[0], f[1]);
    __half2 h1 = __floats2half2_rn(f[2], f[3]);
    __half2 h2 = __floats2half2_rn(f[4], f[5]);
    __half2 h3 = __floats2half2_rn(f[6], f[7]);
    unsigned u0 = *reinterpret_cast<unsigned*>(&h0);
    unsigned u1 = *reinterpret_cast<unsigned*>(&h1);
    unsigned u2 = *reinterpret_cast<unsigned*>(&h2);
    unsigned u3 = *reinterpret_cast<unsigned*>(&h3);

    __half2* dst = g_voxh + ((size_t)b * R3 + sv[l]) * 32 + 4 * w;
    asm volatile("red.global.add.noftz.v4.f16x2 [%0], {%1,%2,%3,%4};"
                 :: "l"(dst), "r"(u0), "r"(u1), "r"(u2), "r"(u3) : "memory");
}

// ----------------------------------------- devoxelize (x1 coords) + concat out
// Block: 256 threads / 8 warps handles 128 points. Within a warp: 4 points
// per iteration, lane l -> point (l>>3), 16B voxel chunk (l&7). One LDG.128
// per warp gathers the full 64-channel row of 4 points' neighbor voxel.
// Accumulation in fp16 (HFMA2), two 4-neighbor chains; 1/max(cnt,1) computed
// inline with fast reciprocal and folded into the fp32 weight.
__global__ __launch_bounds__(256) void devox_kernel(const float* __restrict__ c1,
                                                    float* __restrict__ out) {
    const int b  = blockIdx.y;
    const int n0 = blockIdx.x * 128;
    __shared__ float sm[64 * 129];
    const int tid = threadIdx.x;

    float* outb = out + (size_t)b * 2 * NC * NPTS;

    const float mx = (float)(g_sum[0][b][0] * (1.0 / NPTS));
    const float my = (float)(g_sum[0][b][1] * (1.0 / NPTS));
    const float mz = (float)(g_sum[0][b][2] * (1.0 / NPTS));
    const float k  = 32.0f / (2.0f * sqrtf(__uint_as_float(g_maxn[0][b])));

    const float* cb = c1 + (size_t)b * 3 * NPTS;
    const uint4* voxb = reinterpret_cast<const uint4*>(g_voxh + (size_t)b * R3 * 32);
    const float* cntb = g_cnt + b * R3;

    const int w  = tid >> 5, l = tid & 31;
    const int cg = l & 7;        // 16B chunk -> channels 8cg..8cg+7
    const int pl = l >> 3;       // point within group of 4

    #pragma unroll
    for (int it = 0; it < 4; ++it) {
        const int p = w * 16 + it * 4 + pl;
        const int n = n0 + p;
        const float cx = __ldg(&cb[n]);
        const float cy = __ldg(&cb[NPTS + n]);
        const float cz = __ldg(&cb[2 * NPTS + n]);
        const float ncx = fminf(fmaxf((cx - mx) * k + 16.0f, 0.0f), 31.0f);
        const float ncy = fminf(fmaxf((cy - my) * k + 16.0f, 0.0f), 31.0f);
        const float ncz = fminf(fmaxf((cz - mz) * k + 16.0f, 0.0f), 31.0f);
        const float fx = floorf(ncx), fy = floorf(ncy), fz = floorf(ncz);
        const float dx = ncx - fx,   dy = ncy - fy,   dz = ncz - fz;
        const int x0 = (int)fx, y0 = (int)fy, z0 = (int)fz;
        const int x1i = min(x0 + 1, 31), y1i = min(y0 + 1, 31), z1i = min(z0 + 1, 31);

        __half2 accA[4], accB[4];
        #pragma unroll
        for (int j = 0; j < 4; ++j) {
            accA[j] = __floats2half2_rn(0.f, 0.f);
            accB[j] = __floats2half2_rn(0.f, 0.f);
        }
        #pragma unroll
        for (int kk = 0; kk < 8; ++kk) {
            const int   ix = (kk & 4) ? x1i : x0;  const float wx = (kk & 4) ? dx : 1.0f - dx;
            const int   iy = (kk & 2) ? y1i : y0;  const float wy = (kk & 2) ? dy : 1.0f - dy;
            const int   iz = (kk & 1) ? z1i : z0;  const float wz = (kk & 1) ? dz : 1.0f - dz;
            const int v = (ix * RR + iy) * RR + iz;
            const float rc = __fdividef(1.0f, fmaxf(__ldg(&cntb[v]), 1.0f));
            const __half2 w2 = __float2half2_rn(wx * wy * wz * rc);
            const uint4 g = __ldg(&voxb[v * 8 + cg]);     // 16B = 8 channels
            #pragma unroll
            for (int j = 0; j < 4; ++j) {
                const unsigned uu = (&g.x)[j];
                const __half2 hv = *reinterpret_cast<const __half2*>(&uu);
                if (kk < 4) accA[j] = __hfma2(hv, w2, accA[j]);
                else        accB[j] = __hfma2(hv, w2, accB[j]);
            }
        }
        // combine in fp32, store transposed: bank = 8*cg + j' + p (mod 32) distinct
        #pragma unroll
        for (int j = 0; j < 4; ++j) {
            const float2 a = __half22float2(accA[j]);
            const float2 c2f = __half22float2(accB[j]);
            sm[(8 * cg + 2 * j)     * 129 + p] = a.x + c2f.x;
            sm[(8 * cg + 2 * j + 1) * 129 + p] = a.y + c2f.y;
        }
    }
    __syncthreads();

    // coalesced writeback of devox channels (out channels 64..127), streaming
    #pragma unroll 4
    for (int i = tid; i < 64 * 128; i += 256) {
        const int c = i >> 7, p = i & 127;
        __stcs(&outb[(size_t)(64 + c) * NPTS + n0 + p], sm[c * 129 + p]);
    }
}

extern "C" void kernel_launch(void* const* d_in, const int* in_sizes, int n_in,
                              void* d_out, int out_size) {
    const float* f1 = (const float*)d_in[0];   // x1_features [8,64,65536]
    const float* f2 = (const float*)d_in[1];   // x2_features [8,64,65536]
    const float* c1 = (const float*)d_in[2];   // x1_coords   [8,3,65536]
    const float* c2 = (const float*)d_in[3];   // x2_coords   [8,3,65536]
    float* out = (float*)d_out;                // [8,128,65536]

    // One-time stream/event setup (first call is the non-captured correctness
    // run; later captured calls just reuse them). No device memory involved.
    static cudaStream_t sB = nullptr;
    static cudaEvent_t evFork = nullptr, evJoin = nullptr;
    if (sB == nullptr) {
        cudaStreamCreateWithFlags(&sB, cudaStreamNonBlocking);
        cudaEventCreateWithFlags(&evFork, cudaEventDisableTiming);
        cudaEventCreateWithFlags(&evJoin, cudaEventDisableTiming);
    }

    void *p_voxh, *p_cnt, *p_sum, *p_max;
    cudaGetSymbolAddress(&p_voxh, g_voxh);
    cudaGetSymbolAddress(&p_cnt, g_cnt);
    cudaGetSymbolAddress(&p_sum, g_sum);
    cudaGetSymbolAddress(&p_max, g_maxn);
    cudaMemsetAsync(p_voxh, 0, sizeof(__half2) * NB * R3 * 32);
    cudaMemsetAsync(p_cnt, 0, sizeof(float) * NB * R3);
    cudaMemsetAsync(p_sum, 0, sizeof(double) * 2 * NB * 3);
    cudaMemsetAsync(p_max, 0, sizeof(unsigned int) * 2 * NB);

    // Fork: run the independent x1 -> out copy concurrently on stream B.
    cudaEventRecord(evFork, 0);
    cudaStreamWaitEvent(sB, evFork, 0);
    copy_kernel<<<dim3(NPTS / 128, NB), 256, 0, sB>>>(f1, out);
    cudaEventRecord(evJoin, sB);

    sums_kernel   <<<dim3(32, NB, 2), 256>>>(c1, c2);
    maxnorm_kernel<<<dim3(32, NB, 2), 256>>>(c1, c2);
    vox_kernel    <<<dim3(NPTS / 32, NB), 256>>>(f2, c2);
    devox_kernel  <<<dim3(NPTS / 128, NB), 256>>>(c1, out);

    // Join stream B back into the main stream before capture ends.
    cudaStreamWaitEvent(0, evJoin, 0);
}

// round 17
// speedup vs baseline: 1.1727x; 1.1727x over previous
#include <cuda_runtime.h>
#include <cuda_fp16.h>
#include <cstdint>

#define NB   8
#define NC   64
#define NPTS 65536
#define RR   32
#define R3   32768

#define VOXH_BYTES (NB * R3 * 32 * 4)          // 33554432
#define CNT_BYTES  (NB * R3 * 4)               // 1048576
#define BUF_BYTES  (VOXH_BYTES + CNT_BYTES)    // 34603008

// Scratch (device globals — no allocation allowed)
__device__ __align__(4096) unsigned char g_buf[BUF_BYTES];  // voxh | cnt, one memset
#define G_VOXH ((__half2*)g_buf)
#define G_CNT  ((float*)(g_buf + VOXH_BYTES))

__device__ double       g_psum[2][NB][32][3];  // per-block partial coord sums
__device__ float        g_mean[2][NB][3];      // finalized means
__device__ unsigned int g_maxn[2][NB];         // max ||c-mean||^2 as float bits

__device__ __forceinline__ double warpRedSumD(double v) {
    #pragma unroll
    for (int o = 16; o > 0; o >>= 1) v += __shfl_down_sync(0xffffffffu, v, o);
    return v;
}
__device__ __forceinline__ float warpRedMaxF(float v) {
    #pragma unroll
    for (int o = 16; o > 0; o >>= 1) v = fmaxf(v, __shfl_down_sync(0xffffffffu, v, o));
    return v;
}

// ------------------------------------------------- stats pass 1: partial sums
__global__ void sums_kernel(const float* __restrict__ c1, const float* __restrict__ c2) {
    const int t = blockIdx.z, b = blockIdx.y;
    if (blockIdx.x == 0 && threadIdx.x == 0) g_maxn[t][b] = 0u;  // init for pass 2
    const float* c = (t == 0 ? c1 : c2) + (size_t)b * 3 * NPTS;
    double sx = 0.0, sy = 0.0, sz = 0.0;
    for (int i = blockIdx.x * blockDim.x + threadIdx.x; i < NPTS; i += gridDim.x * blockDim.x) {
        sx += (double)c[i];
        sy += (double)c[NPTS + i];
        sz += (double)c[2 * NPTS + i];
    }
    sx = warpRedSumD(sx); sy = warpRedSumD(sy); sz = warpRedSumD(sz);
    __shared__ double sh[3][8];
    const int w = threadIdx.x >> 5, l = threadIdx.x & 31;
    if (l == 0) { sh[0][w] = sx; sh[1][w] = sy; sh[2][w] = sz; }
    __syncthreads();
    if (threadIdx.x == 0) {
        double a = 0, d = 0, e = 0;
        #pragma unroll
        for (int i = 0; i < 8; i++) { a += sh[0][i]; d += sh[1][i]; e += sh[2][i]; }
        g_psum[t][b][blockIdx.x][0] = a;
        g_psum[t][b][blockIdx.x][1] = d;
        g_psum[t][b][blockIdx.x][2] = e;
    }
}

// ---------------------------- stats pass 2: finalize mean, partial max norm^2
__global__ void maxnorm_kernel(const float* __restrict__ c1, const float* __restrict__ c2) {
    const int t = blockIdx.z, b = blockIdx.y;
    __shared__ float s_mean[3];
    if (threadIdx.x < 32) {
        double px = g_psum[t][b][threadIdx.x][0];
        double py = g_psum[t][b][threadIdx.x][1];
        double pz = g_psum[t][b][threadIdx.x][2];
        px = warpRedSumD(px); py = warpRedSumD(py); pz = warpRedSumD(pz);
        if (threadIdx.x == 0) {
            s_mean[0] = (float)(px * (1.0 / NPTS));
            s_mean[1] = (float)(py * (1.0 / NPTS));
            s_mean[2] = (float)(pz * (1.0 / NPTS));
            if (blockIdx.x == 0) {
                g_mean[t][b][0] = s_mean[0];
                g_mean[t][b][1] = s_mean[1];
                g_mean[t][b][2] = s_mean[2];
            }
        }
    }
    __syncthreads();
    const float mx = s_mean[0], my = s_mean[1], mz = s_mean[2];
    const float* c = (t == 0 ? c1 : c2) + (size_t)b * 3 * NPTS;
    float m = 0.0f;
    for (int i = blockIdx.x * blockDim.x + threadIdx.x; i < NPTS; i += gridDim.x * blockDim.x) {
        const float dx = c[i] - mx, dy = c[NPTS + i] - my, dz = c[2 * NPTS + i] - mz;
        m = fmaxf(m, dx * dx + dy * dy + dz * dz);
    }
    m = warpRedMaxF(m);
    __shared__ float sh[8];
    const int w = threadIdx.x >> 5, l = threadIdx.x & 31;
    if (l == 0) sh[w] = m;
    __syncthreads();
    if (threadIdx.x == 0) {
        float mm = sh[0];
        #pragma unroll
        for (int i = 1; i < 8; i++) mm = fmaxf(mm, sh[i]);
        atomicMax(&g_maxn[t][b], __float_as_uint(mm));
    }
}

// ---------------------------------------- voxelize (x2) + x1 passthrough copy
// Block: 256 threads, 32 points. Warp w handles channels 8w..8w+7, lane = point.
// fp16x2 vector reduction: one REDG.128 covers 8 channels. The independent
// x1 -> out copy streams through the REDG latency shadow. All read-once
// traffic uses streaming hints to keep voxh/cnt resident in L2 for devox.
__global__ __launch_bounds__(256) void vox_kernel(const float* __restrict__ f2,
                                                  const float* __restrict__ c2,
                                                  const float* __restrict__ f1,
                                                  float* __restrict__ out) {
    const int b  = blockIdx.y;
    const int n0 = blockIdx.x * 32;
    __shared__ int sv[32];
    const int tid = threadIdx.x;

    if (tid < 32) {
        const float* cb = c2 + (size_t)b * 3 * NPTS;
        const float mx = g_mean[1][b][0];
        const float my = g_mean[1][b][1];
        const float mz = g_mean[1][b][2];
        const float k  = 32.0f / (2.0f * sqrtf(__uint_as_float(g_maxn[1][b])));
        const int n = n0 + tid;
        const float ncx = fminf(fmaxf((cb[n]            - mx) * k + 16.0f, 0.0f), 31.0f);
        const float ncy = fminf(fmaxf((cb[NPTS + n]     - my) * k + 16.0f, 0.0f), 31.0f);
        const float ncz = fminf(fmaxf((cb[2 * NPTS + n] - mz) * k + 16.0f, 0.0f), 31.0f);
        const int v = ((int)rintf(ncx) * RR + (int)rintf(ncy)) * RR + (int)rintf(ncz);
        sv[tid] = v;
        atomicAdd(&G_CNT[b * R3 + v], 1.0f);
    }
    __syncthreads();

    const int w = tid >> 5, l = tid & 31;   // w: 0..7 channel groups of 8
    const int n = n0 + l;
    const float* fb = f2 + (size_t)b * NC * NPTS + (size_t)(8 * w) * NPTS + n;
    float f[8];
    #pragma unroll
    for (int j = 0; j < 8; ++j) f[j] = __ldcs(&fb[(size_t)j * NPTS]);

    __half2 h0 = __floats2half2_rn(f[0], f[1]);
    __half2 h1 = __floats2half2_rn(f[2], f[3]);
    __half2 h2 = __floats2half2_rn(f[4], f[5]);
    __half2 h3 = __floats2half2_rn(f[6], f[7]);
    unsigned u0 = *reinterpret_cast<unsigned*>(&h0);
    unsigned u1 = *reinterpret_cast<unsigned*>(&h1);
    unsigned u2 = *reinterpret_cast<unsigned*>(&h2);
    unsigned u3 = *reinterpret_cast<unsigned*>(&h3);

    __half2* dst = G_VOXH + ((size_t)b * R3 + sv[l]) * 32 + 4 * w;
    asm volatile("red.global.add.noftz.v4.f16x2 [%0], {%1,%2,%3,%4};"
                 :: "l"(dst), "r"(u0), "r"(u1), "r"(u2), "r"(u3) : "memory");

    // x1 passthrough copy for this block's 32-point tile (independent work,
    // hides under the REDG shadow). 512 float4 units, 2 per thread.
    const float* f1b = f1 + (size_t)b * NC * NPTS;
    float* outb = out + (size_t)b * 2 * NC * NPTS;
    #pragma unroll
    for (int i = tid; i < 64 * 8; i += 256) {
        const int c = i >> 3, j = i & 7;
        const float4 v = __ldcs(((const float4*)(f1b + (size_t)c * NPTS + n0)) + j);
        __stcs(((float4*)(outb + (size_t)c * NPTS + n0)) + j, v);
    }
}

// ----------------------------------------- devoxelize (x1 coords) + concat out
// Block: 256 threads / 8 warps handles 128 points. Within a warp: 4 points
// per iteration, lane l -> point (l>>3), 16B voxel chunk (l&7). One LDG.128
// per warp gathers the full 64-channel row of 4 points' neighbor voxel.
// Accumulation in fp16 (HFMA2), two 4-neighbor chains; 1/max(cnt,1) computed
// inline with fast reciprocal and folded into the fp32 weight.
__global__ __launch_bounds__(256) void devox_kernel(const float* __restrict__ c1,
                                                    float* __restrict__ out) {
    const int b  = blockIdx.y;
    const int n0 = blockIdx.x * 128;
    __shared__ float sm[64 * 129];
    const int tid = threadIdx.x;

    float* outb = out + (size_t)b * 2 * NC * NPTS;

    const float mx = g_mean[0][b][0];
    const float my = g_mean[0][b][1];
    const float mz = g_mean[0][b][2];
    const float k  = 32.0f / (2.0f * sqrtf(__uint_as_float(g_maxn[0][b])));

    const float* cb = c1 + (size_t)b * 3 * NPTS;
    const uint4* voxb = reinterpret_cast<const uint4*>(G_VOXH + (size_t)b * R3 * 32);
    const float* cntb = G_CNT + b * R3;

    const int w  = tid >> 5, l = tid & 31;
    const int cg = l & 7;        // 16B chunk -> channels 8cg..8cg+7
    const int pl = l >> 3;       // point within group of 4

    #pragma unroll
    for (int it = 0; it < 4; ++it) {
        const int p = w * 16 + it * 4 + pl;
        const int n = n0 + p;
        const float cx = __ldg(&cb[n]);
        const float cy = __ldg(&cb[NPTS + n]);
        const float cz = __ldg(&cb[2 * NPTS + n]);
        const float ncx = fminf(fmaxf((cx - mx) * k + 16.0f, 0.0f), 31.0f);
        const float ncy = fminf(fmaxf((cy - my) * k + 16.0f, 0.0f), 31.0f);
        const float ncz = fminf(fmaxf((cz - mz) * k + 16.0f, 0.0f), 31.0f);
        const float fx = floorf(ncx), fy = floorf(ncy), fz = floorf(ncz);
        const float dx = ncx - fx,   dy = ncy - fy,   dz = ncz - fz;
        const int x0 = (int)fx, y0 = (int)fy, z0 = (int)fz;
        const int x1i = min(x0 + 1, 31), y1i = min(y0 + 1, 31), z1i = min(z0 + 1, 31);

        __half2 accA[4], accB[4];
        #pragma unroll
        for (int j = 0; j < 4; ++j) {
            accA[j] = __floats2half2_rn(0.f, 0.f);
            accB[j] = __floats2half2_rn(0.f, 0.f);
        }
        #pragma unroll
        for (int kk = 0; kk < 8; ++kk) {
            const int   ix = (kk & 4) ? x1i : x0;  const float wx = (kk & 4) ? dx : 1.0f - dx;
            const int   iy = (kk & 2) ? y1i : y0;  const float wy = (kk & 2) ? dy : 1.0f - dy;
            const int   iz = (kk & 1) ? z1i : z0;  const float wz = (kk & 1) ? dz : 1.0f - dz;
            const int v = (ix * RR + iy) * RR + iz;
            const float rc = __fdividef(1.0f, fmaxf(__ldg(&cntb[v]), 1.0f));
            const __half2 w2 = __float2half2_rn(wx * wy * wz * rc);
            const uint4 g = __ldg(&voxb[v * 8 + cg]);     // 16B = 8 channels
            #pragma unroll
            for (int j = 0; j < 4; ++j) {
                const unsigned uu = (&g.x)[j];
                const __half2 hv = *reinterpret_cast<const __half2*>(&uu);
                if (kk < 4) accA[j] = __hfma2(hv, w2, accA[j]);
                else        accB[j] = __hfma2(hv, w2, accB[j]);
            }
        }
        // combine in fp32, store transposed: bank = 8*cg + j' + p (mod 32) distinct
        #pragma unroll
        for (int j = 0; j < 4; ++j) {
            const float2 a = __half22float2(accA[j]);
            const float2 c2f = __half22float2(accB[j]);
            sm[(8 * cg + 2 * j)     * 129 + p] = a.x + c2f.x;
            sm[(8 * cg + 2 * j + 1) * 129 + p] = a.y + c2f.y;
        }
    }
    __syncthreads();

    // coalesced writeback of devox channels (out channels 64..127), streaming
    #pragma unroll 4
    for (int i = tid; i < 64 * 128; i += 256) {
        const int c = i >> 7, p = i & 127;
        __stcs(&outb[(size_t)(64 + c) * NPTS + n0 + p], sm[c * 129 + p]);
    }
}

extern "C" void kernel_launch(void* const* d_in, const int* in_sizes, int n_in,
                              void* d_out, int out_size) {
    const float* f1 = (const float*)d_in[0];   // x1_features [8,64,65536]
    const float* f2 = (const float*)d_in[1];   // x2_features [8,64,65536]
    const float* c1 = (const float*)d_in[2];   // x1_coords   [8,3,65536]
    const float* c2 = (const float*)d_in[3];   // x2_coords   [8,3,65536]
    float* out = (float*)d_out;                // [8,128,65536]

    void* p_buf;
    cudaGetSymbolAddress(&p_buf, g_buf);
    cudaMemsetAsync(p_buf, 0, BUF_BYTES);      // voxh + cnt in one shot

    sums_kernel   <<<dim3(32, NB, 2), 256>>>(c1, c2);
    maxnorm_kernel<<<dim3(32, NB, 2), 256>>>(c1, c2);
    vox_kernel    <<<dim3(NPTS / 32, NB), 256>>>(f2, c2, f1, out);
    devox_kernel  <<<dim3(NPTS / 128, NB), 256>>>(c1, out);
}